// round 14
// baseline (speedup 1.0000x reference)
#include <cuda_runtime.h>
#include <cuda_fp16.h>
#include <cstdint>

#define NROWS 8192
#define DIN   512
#define DOUT  512

#define CTAM 128
#define CTAN 256
#define CTAK 32

// ---- warp-autonomous pipeline geometry ----
#define WSTAGE 3
#define WSLICE 8192                  // per warp per stage: A 4096B + B 4096B
#define WARP_SMEM (WSTAGE * WSLICE)  // 24576
#define DYN_SMEMW (8 * WARP_SMEM)    // 196608

#define NT1 (NROWS / CTAK)           // 256
#define NT2 (DIN / CTAK)             // 16

// Scratch (allocation-free)
__device__ __half g_adj_h[(size_t)NROWS * NROWS];
__device__ float  g_deg[NROWS];
__device__ __half g_xsT[(size_t)DIN * NROWS];
__device__ __half g_support[(size_t)NROWS * DIN];
__device__ __half g_Wh[(size_t)DOUT * DIN];

// ======================= PTX helpers =======================
__device__ __forceinline__ uint32_t smem_u32(const void* p) {
    uint32_t a;
    asm("{ .reg .u64 t; cvta.to.shared.u64 t, %1; cvt.u32.u64 %0, t; }" : "=r"(a) : "l"(p));
    return a;
}

__device__ __forceinline__ uint32_t h2_bits(__half2 h) {
    return *reinterpret_cast<uint32_t*>(&h);
}

#define CP_ASYNC16_CA(dst, src) \
    asm volatile("cp.async.ca.shared.global [%0], [%1], 16;" :: "r"(dst), "l"(src))
#define CP_COMMIT() asm volatile("cp.async.commit_group;" ::: "memory")
#define CP_WAITG1() asm volatile("cp.async.wait_group 1;" ::: "memory")

#define LDSM4(r0, r1, r2, r3, addr)                                             \
    asm volatile("ldmatrix.sync.aligned.m8n8.x4.shared.b16 {%0,%1,%2,%3}, [%4];"\
                 : "=r"(r0), "=r"(r1), "=r"(r2), "=r"(r3) : "r"(addr))

#define MMA_F16(d, a, b0, b1)                                                   \
    asm volatile(                                                               \
        "mma.sync.aligned.m16n8k16.row.col.f32.f16.f16.f32 "                    \
        "{%0,%1,%2,%3}, {%4,%5,%6,%7}, {%8,%9}, {%0,%1,%2,%3};"                 \
        : "+f"((d)[0]), "+f"((d)[1]), "+f"((d)[2]), "+f"((d)[3])                \
        : "r"((a)[0]), "r"((a)[1]), "r"((a)[2]), "r"((a)[3]),                   \
          "r"(b0), "r"(b1))

// ---------------------------------------------------------------------------
// Kernel 1: d[i] = rsqrt(1 + sum_j adj[i][j])  AND  g_adj_h = half(adj)
// ---------------------------------------------------------------------------
__global__ __launch_bounds__(256) void rowsum_convert(const float* __restrict__ adj) {
    const int row = blockIdx.x;
    const float4* p = reinterpret_cast<const float4*>(adj + (size_t)row * NROWS);
    uint4* dst = reinterpret_cast<uint4*>(g_adj_h + (size_t)row * NROWS);
    float s = 0.f;
#pragma unroll 4
    for (int i = threadIdx.x; i < NROWS / 8; i += 256) {
        float4 v0 = __ldcs(&p[2 * i + 0]);
        float4 v1 = __ldcs(&p[2 * i + 1]);
        s += ((v0.x + v0.y) + (v0.z + v0.w)) + ((v1.x + v1.y) + (v1.z + v1.w));
        uint4 o;
        o.x = h2_bits(__floats2half2_rn(v0.x, v0.y));
        o.y = h2_bits(__floats2half2_rn(v0.z, v0.w));
        o.z = h2_bits(__floats2half2_rn(v1.x, v1.y));
        o.w = h2_bits(__floats2half2_rn(v1.z, v1.w));
        __stcs(&dst[i], o);
    }
#pragma unroll
    for (int o = 16; o > 0; o >>= 1) s += __shfl_xor_sync(0xffffffffu, s, o);
    __shared__ float ws[8];
    if ((threadIdx.x & 31) == 0) ws[threadIdx.x >> 5] = s;
    __syncthreads();
    if (threadIdx.x == 0) {
        float t = 0.f;
#pragma unroll
        for (int i = 0; i < 8; i++) t += ws[i];
        g_deg[row] = rsqrtf(1.0f + t);
    }
}

// ---------------------------------------------------------------------------
// Kernel 2: xsT[n][k] = half( d_k * x[k][n] )
// ---------------------------------------------------------------------------
__global__ __launch_bounds__(256) void scale_transpose_h(const float* __restrict__ x) {
    __shared__ float tile[32][33];
    const int kb = blockIdx.x * 32;
    const int nb = blockIdx.y * 32;
    const int tx = threadIdx.x & 31;
    const int ty = threadIdx.x >> 5;
#pragma unroll
    for (int i = 0; i < 32; i += 8) {
        int k = kb + ty + i;
        tile[ty + i][tx] = g_deg[k] * x[(size_t)k * DIN + nb + tx];
    }
    __syncthreads();
#pragma unroll
    for (int i = 0; i < 32; i += 8) {
        int n = nb + ty + i;
        g_xsT[(size_t)n * NROWS + kb + tx] = __float2half_rn(tile[tx][ty + i]);
    }
}

// ---------------------------------------------------------------------------
// Kernel 3: W fp32 -> fp16
// ---------------------------------------------------------------------------
__global__ __launch_bounds__(256) void w_convert(const float* __restrict__ W) {
    const int i = blockIdx.x * 256 + threadIdx.x;
    float4 v = reinterpret_cast<const float4*>(W)[i];
    __half2* d = reinterpret_cast<__half2*>(g_Wh) + 2 * i;
    d[0] = __floats2half2_rn(v.x, v.y);
    d[1] = __floats2half2_rn(v.z, v.w);
}

// ===========================================================================
// Warp-autonomous gemm core. Each warp owns a 64x64 output tile and a private
// 3-stage smem pipeline holding ITS A (64x32) and B (64x32) slices. No
// __syncthreads in the mainloop: cp.async groups are per-thread.
// Physical layout per slice: 64 rows x 64B, 16B-granule XOR swizzle
//   phys_q = logical_q ^ ((row>>1)&3)
// applied identically at store (cp.async) and load (ldmatrix) time.
// ===========================================================================

// Load this warp's A+B slices for k-tile t. 8 cp.async per operand per lane.
__device__ __forceinline__ void wload(uint32_t ws,
                                      const __half* __restrict__ Ag, int sA,
                                      const __half* __restrict__ Bg, int sB,
                                      int mbase, int nbase, int t) {
    const int l = threadIdx.x & 31;
    const int k0 = t * CTAK;
    const uint32_t st = ws + (uint32_t)(t % WSTAGE) * WSLICE;
    const int r4 = l >> 2;                 // row within 8-row group
    const int q = l & 3;                   // logical 16B column
    // (row>>1)&3 = (l>>3)&3 for row = 8j + r4 (lane-constant xor)
    const uint32_t dq = (uint32_t)(r4 * 64 + ((q ^ ((l >> 3) & 3)) * 16));
#pragma unroll
    for (int j = 0; j < 8; j++)
        CP_ASYNC16_CA(st + dq + j * 512,
                      Ag + (size_t)(mbase + 8 * j + r4) * sA + k0 + q * 8);
#pragma unroll
    for (int j = 0; j < 8; j++)
        CP_ASYNC16_CA(st + 4096 + dq + j * 512,
                      Bg + (size_t)(nbase + 8 * j + r4) * sB + k0 + q * 8);
}

// Fragments for k-half s of tile t from this warp's slices.
__device__ __forceinline__ void wfrags(uint32_t ws, int t, int s,
                                       uint32_t a[4][4], uint32_t b[8][2]) {
    const int l = threadIdx.x & 31;
    const uint32_t st = ws + (uint32_t)(t % WSTAGE) * WSLICE;
    const int rlA = l & 15, hiA = (l >> 4) & 1, xA = (rlA >> 1) & 3;
    const uint32_t ao = st + (uint32_t)(rlA * 64 + (((2 * s + hiA) ^ xA) * 16));
#pragma unroll
    for (int i = 0; i < 4; i++)
        LDSM4(a[i][0], a[i][1], a[i][2], a[i][3], ao + i * 1024);
    const int rb = (l & 7) + ((l >> 4) & 1) * 8, hib = (l >> 3) & 1, xB = (rb >> 1) & 3;
    const uint32_t bo = st + 4096 + (uint32_t)(rb * 64 + (((2 * s + hib) ^ xB) * 16));
#pragma unroll
    for (int jp = 0; jp < 4; jp++)
        LDSM4(b[2 * jp][0], b[2 * jp][1], b[2 * jp + 1][0], b[2 * jp + 1][1],
              bo + jp * 1024);
}

__device__ __forceinline__ void mma_all(float acc[4][8][4],
                                        uint32_t a[4][4], uint32_t b[8][2]) {
#pragma unroll
    for (int i = 0; i < 4; i++)
#pragma unroll
        for (int j = 0; j < 8; j++)
            MMA_F16(acc[i][j], a[i], b[j][0], b[j][1]);
}

// Barrier-free per-warp mainloop. Stage slot (t+2)%3 held tile t-1, whose
// fragments were consumed by mma issued in iteration t-1 (same-warp program
// order + scoreboard) -> safe to overwrite. Uniform commits: at iter t,
// issued groups = t+3 (tiles 0..t+2); wait_group 1 => tiles 0..t+1 resident.
__device__ __forceinline__ void wgemm(uint32_t ws,
                                      const __half* __restrict__ Ag, int sA,
                                      const __half* __restrict__ Bg, int sB,
                                      int mbase, int nbase, int nt,
                                      float acc[4][8][4]) {
    wload(ws, Ag, sA, Bg, sB, mbase, nbase, 0);
    CP_COMMIT();
    wload(ws, Ag, sA, Bg, sB, mbase, nbase, 1);
    CP_COMMIT();
    CP_WAITG1();                 // tile 0 resident

    uint32_t a0[4][4], b0[8][2], a1[4][4], b1[8][2];
    wfrags(ws, 0, 0, a0, b0);

    for (int t = 0; t < nt; t++) {
        if (t + 2 < nt)
            wload(ws, Ag, sA, Bg, sB, mbase, nbase, t + 2);
        CP_COMMIT();
        wfrags(ws, t, 1, a1, b1);
        mma_all(acc, a0, b0);
        if (t + 1 < nt) {
            CP_WAITG1();         // tile t+1 resident (per-warp groups)
            wfrags(ws, t + 1, 0, a0, b0);
        }
        mma_all(acc, a1, b1);
    }
}

// ---------------------------------------------------------------------------
// Kernel 4: support = d_i * ( adj_h @ xsT^T + d_i * x_i )   -> fp16
// ---------------------------------------------------------------------------
__global__ __launch_bounds__(256, 1) void gemm1_h(const float* __restrict__ x) {
    extern __shared__ __align__(128) char dyn[];
    const int tid = threadIdx.x;
    const int wid = tid >> 5;
    const int lane = tid & 31;
    const int m0 = (blockIdx.x >> 1) * CTAM;
    const int n0 = (blockIdx.x & 1) * CTAN;
    const int wm = (wid & 1) * 64;
    const int wn = (wid >> 1) * 64;
    const uint32_t ws = smem_u32(dyn) + (uint32_t)wid * WARP_SMEM;

    float acc[4][8][4];
#pragma unroll
    for (int i = 0; i < 4; i++)
#pragma unroll
        for (int j = 0; j < 8; j++)
#pragma unroll
            for (int q = 0; q < 4; q++) acc[i][j][q] = 0.f;

    wgemm(ws, g_adj_h, NROWS, g_xsT, NROWS, m0 + wm, n0 + wn, NT1, acc);

    // epilogue: support = half( d_m * (acc + d_m * x) )
    const int g = lane >> 2, tg = lane & 3;
#pragma unroll
    for (int i = 0; i < 4; i++) {
        const int r0 = m0 + wm + 16 * i + g;
        const int r1 = r0 + 8;
        const float d0 = g_deg[r0], d1 = g_deg[r1];
#pragma unroll
        for (int j = 0; j < 8; j++) {
            const int col = n0 + wn + 8 * j + 2 * tg;
            float2 x0 = *reinterpret_cast<const float2*>(&x[(size_t)r0 * DIN + col]);
            float2 x1 = *reinterpret_cast<const float2*>(&x[(size_t)r1 * DIN + col]);
            __half2 h0 = __floats2half2_rn(d0 * (acc[i][j][0] + d0 * x0.x),
                                           d0 * (acc[i][j][1] + d0 * x0.y));
            __half2 h1 = __floats2half2_rn(d1 * (acc[i][j][2] + d1 * x1.x),
                                           d1 * (acc[i][j][3] + d1 * x1.y));
            *reinterpret_cast<__half2*>(&g_support[(size_t)r0 * DIN + col]) = h0;
            *reinterpret_cast<__half2*>(&g_support[(size_t)r1 * DIN + col]) = h1;
        }
    }
}

// ---------------------------------------------------------------------------
// Kernel 5: out = relu(support @ Wh^T + b)   -> fp32
// ---------------------------------------------------------------------------
__global__ __launch_bounds__(256, 1) void gemm2_h(const float* __restrict__ bias,
                                                  float* __restrict__ out) {
    extern __shared__ __align__(128) char dyn[];
    const int tid = threadIdx.x;
    const int wid = tid >> 5;
    const int lane = tid & 31;
    const int m0 = (blockIdx.x >> 1) * CTAM;
    const int n0 = (blockIdx.x & 1) * CTAN;
    const int wm = (wid & 1) * 64;
    const int wn = (wid >> 1) * 64;
    const uint32_t ws = smem_u32(dyn) + (uint32_t)wid * WARP_SMEM;

    float acc[4][8][4];
#pragma unroll
    for (int i = 0; i < 4; i++)
#pragma unroll
        for (int j = 0; j < 8; j++)
#pragma unroll
            for (int q = 0; q < 4; q++) acc[i][j][q] = 0.f;

    wgemm(ws, g_support, DIN, g_Wh, DIN, m0 + wm, n0 + wn, NT2, acc);

    const int g = lane >> 2, tg = lane & 3;
#pragma unroll
    for (int i = 0; i < 4; i++) {
        const int r0 = m0 + wm + 16 * i + g;
        const int r1 = r0 + 8;
#pragma unroll
        for (int j = 0; j < 8; j++) {
            const int col = n0 + wn + 8 * j + 2 * tg;
            float2 bv = *reinterpret_cast<const float2*>(&bias[col]);
            float2 o0, o1;
            o0.x = fmaxf(acc[i][j][0] + bv.x, 0.f);
            o0.y = fmaxf(acc[i][j][1] + bv.y, 0.f);
            o1.x = fmaxf(acc[i][j][2] + bv.x, 0.f);
            o1.y = fmaxf(acc[i][j][3] + bv.y, 0.f);
            *reinterpret_cast<float2*>(&out[(size_t)r0 * DOUT + col]) = o0;
            *reinterpret_cast<float2*>(&out[(size_t)r1 * DOUT + col]) = o1;
        }
    }
}

// ---------------------------------------------------------------------------
extern "C" void kernel_launch(void* const* d_in, const int* in_sizes, int n_in,
                              void* d_out, int out_size) {
    const float* x = nullptr;
    const float* adj = nullptr;
    const float* W = nullptr;
    const float* b = nullptr;
    for (int i = 0; i < n_in; i++) {
        long sz = (long)in_sizes[i];
        if (sz == (long)NROWS * NROWS)      adj = (const float*)d_in[i];
        else if (sz == (long)NROWS * DIN)   x   = (const float*)d_in[i];
        else if (sz == (long)DIN * DOUT)    W   = (const float*)d_in[i];
        else if (sz == (long)DOUT)          b   = (const float*)d_in[i];
    }
    float* out = (float*)d_out;

    cudaFuncSetAttribute(gemm1_h, cudaFuncAttributeMaxDynamicSharedMemorySize, DYN_SMEMW);
    cudaFuncSetAttribute(gemm2_h, cudaFuncAttributeMaxDynamicSharedMemorySize, DYN_SMEMW);

    rowsum_convert<<<NROWS, 256>>>(adj);
    scale_transpose_h<<<dim3(NROWS / 32, DIN / 32), 256>>>(x);
    w_convert<<<(DOUT * DIN / 4) / 256, 256>>>(W);
    gemm1_h<<<(NROWS / CTAM) * (DIN / CTAN), 256, DYN_SMEMW>>>(x);
    gemm2_h<<<(NROWS / CTAM) * (DOUT / CTAN), 256, DYN_SMEMW>>>(b, out);
}

// round 16
// speedup vs baseline: 1.3541x; 1.3541x over previous
#include <cuda_runtime.h>
#include <cuda_fp16.h>
#include <cstdint>

#define NROWS 8192
#define DIN   512
#define DOUT  512

// ---------------- fp16 mma.sync gemm tiling (R4 geometry) ----------------
#define CTAM 128
#define CTAN 256
#define CTAK 32
#define NSTAGE 4
#define ROWB 80                     // 32 halves data + 16B pad
#define ABYTES (CTAM * ROWB)        // 10240
#define BBYTES (CTAN * ROWB)        // 20480
#define STAGEB (ABYTES + BBYTES)    // 30720
#define DYN_SMEM (STAGEB * NSTAGE)  // 122880

#define NT1 (NROWS / CTAK)          // 256 k-tiles for gemm1
#define NT2 (DIN / CTAK)            // 16 k-tiles for gemm2

// Scratch (allocation-free)
__device__ __half g_adj_h[(size_t)NROWS * NROWS];    // fp16 adjacency
__device__ float  g_deg[NROWS];
__device__ __half g_xsT[(size_t)DIN * NROWS];        // xsT[n][k] = half(d_k * x[k][n])
__device__ __half g_support[(size_t)NROWS * DIN];    // fp16 intermediate
__device__ __half g_Wh[(size_t)DOUT * DIN];          // fp16 weights [n][k]

// ======================= PTX helpers =======================
__device__ __forceinline__ uint32_t smem_u32(const void* p) {
    uint32_t a;
    asm("{ .reg .u64 t; cvta.to.shared.u64 t, %1; cvt.u32.u64 %0, t; }" : "=r"(a) : "l"(p));
    return a;
}

__device__ __forceinline__ uint32_t h2_bits(__half2 h) {
    return *reinterpret_cast<uint32_t*>(&h);
}

#define CP_ASYNC16(dst, src) \
    asm volatile("cp.async.cg.shared.global [%0], [%1], 16;" :: "r"(dst), "l"(src))
#define CP_COMMIT() asm volatile("cp.async.commit_group;" ::: "memory")
#define CP_WAITG2() asm volatile("cp.async.wait_group 2;" ::: "memory")

#define LDSM4(r0, r1, r2, r3, addr)                                             \
    asm volatile("ldmatrix.sync.aligned.m8n8.x4.shared.b16 {%0,%1,%2,%3}, [%4];"\
                 : "=r"(r0), "=r"(r1), "=r"(r2), "=r"(r3) : "r"(addr))

#define MMA_F16(d, a, b0, b1)                                                   \
    asm volatile(                                                               \
        "mma.sync.aligned.m16n8k16.row.col.f32.f16.f16.f32 "                    \
        "{%0,%1,%2,%3}, {%4,%5,%6,%7}, {%8,%9}, {%0,%1,%2,%3};"                 \
        : "+f"((d)[0]), "+f"((d)[1]), "+f"((d)[2]), "+f"((d)[3])                \
        : "r"((a)[0]), "r"((a)[1]), "r"((a)[2]), "r"((a)[3]),                   \
          "r"(b0), "r"(b1))

// ---------------------------------------------------------------------------
// Kernel 1: d[i] = rsqrt(1 + sum_j adj[i][j])  AND  g_adj_h = half(adj)
//   Two rows per block (independent streams -> 2x MLP), streaming ld/st.
// ---------------------------------------------------------------------------
__global__ __launch_bounds__(256) void rowsum_convert(const float* __restrict__ adj) {
    const int row0 = blockIdx.x * 2;
    const int row1 = row0 + 1;
    const float4* p0 = reinterpret_cast<const float4*>(adj + (size_t)row0 * NROWS);
    const float4* p1 = reinterpret_cast<const float4*>(adj + (size_t)row1 * NROWS);
    uint4* d0 = reinterpret_cast<uint4*>(g_adj_h + (size_t)row0 * NROWS);
    uint4* d1 = reinterpret_cast<uint4*>(g_adj_h + (size_t)row1 * NROWS);
    float s0 = 0.f, s1 = 0.f;
#pragma unroll 2
    for (int i = threadIdx.x; i < NROWS / 8; i += 256) {
        float4 a0 = __ldcs(&p0[2 * i + 0]);
        float4 a1 = __ldcs(&p0[2 * i + 1]);
        float4 b0 = __ldcs(&p1[2 * i + 0]);
        float4 b1 = __ldcs(&p1[2 * i + 1]);
        s0 += ((a0.x + a0.y) + (a0.z + a0.w)) + ((a1.x + a1.y) + (a1.z + a1.w));
        s1 += ((b0.x + b0.y) + (b0.z + b0.w)) + ((b1.x + b1.y) + (b1.z + b1.w));
        uint4 oa, ob;
        oa.x = h2_bits(__floats2half2_rn(a0.x, a0.y));
        oa.y = h2_bits(__floats2half2_rn(a0.z, a0.w));
        oa.z = h2_bits(__floats2half2_rn(a1.x, a1.y));
        oa.w = h2_bits(__floats2half2_rn(a1.z, a1.w));
        ob.x = h2_bits(__floats2half2_rn(b0.x, b0.y));
        ob.y = h2_bits(__floats2half2_rn(b0.z, b0.w));
        ob.z = h2_bits(__floats2half2_rn(b1.x, b1.y));
        ob.w = h2_bits(__floats2half2_rn(b1.z, b1.w));
        __stcs(&d0[i], oa);
        __stcs(&d1[i], ob);
    }
#pragma unroll
    for (int o = 16; o > 0; o >>= 1) {
        s0 += __shfl_xor_sync(0xffffffffu, s0, o);
        s1 += __shfl_xor_sync(0xffffffffu, s1, o);
    }
    __shared__ float ws0[8], ws1[8];
    if ((threadIdx.x & 31) == 0) {
        ws0[threadIdx.x >> 5] = s0;
        ws1[threadIdx.x >> 5] = s1;
    }
    __syncthreads();
    if (threadIdx.x == 0) {
        float t0 = 0.f, t1 = 0.f;
#pragma unroll
        for (int i = 0; i < 8; i++) { t0 += ws0[i]; t1 += ws1[i]; }
        g_deg[row0] = rsqrtf(1.0f + t0);
        g_deg[row1] = rsqrtf(1.0f + t1);
    }
}

// ---------------------------------------------------------------------------
// Kernel 2: xsT[n][k] = half( d_k * x[k][n] )   (scaled transpose)
// ---------------------------------------------------------------------------
__global__ __launch_bounds__(256) void scale_transpose_h(const float* __restrict__ x) {
    __shared__ float tile[32][33];
    const int kb = blockIdx.x * 32;
    const int nb = blockIdx.y * 32;
    const int tx = threadIdx.x & 31;
    const int ty = threadIdx.x >> 5;
#pragma unroll
    for (int i = 0; i < 32; i += 8) {
        int k = kb + ty + i;
        tile[ty + i][tx] = g_deg[k] * x[(size_t)k * DIN + nb + tx];
    }
    __syncthreads();
#pragma unroll
    for (int i = 0; i < 32; i += 8) {
        int n = nb + ty + i;
        g_xsT[(size_t)n * NROWS + kb + tx] = __float2half_rn(tile[tx][ty + i]);
    }
}

// ---------------------------------------------------------------------------
// Kernel 3: W fp32 -> fp16
// ---------------------------------------------------------------------------
__global__ __launch_bounds__(256) void w_convert(const float* __restrict__ W) {
    const int i = blockIdx.x * 256 + threadIdx.x;
    float4 v = reinterpret_cast<const float4*>(W)[i];
    __half2* d = reinterpret_cast<__half2*>(g_Wh) + 2 * i;
    d[0] = __floats2half2_rn(v.x, v.y);
    d[1] = __floats2half2_rn(v.z, v.w);
}

// ===========================================================================
// Gemm core (EXACT R4): CTA 128x256, 8 warps (2m x 4n) of 64x64, BK=32,
// 4-stage cp.async, double-buffered ldmatrix fragments.
// ===========================================================================
struct GemmCore {
    uint32_t sbase;
    int m0, n0, wm, wn, lane;
    uint32_t aoff, boff;
};

__device__ __forceinline__ void core_init(GemmCore& c, char* dyn, int bid) {
    const int tid = threadIdx.x;
    const int wid = tid >> 5;
    c.lane = tid & 31;
    c.m0 = (bid >> 1) * CTAM;
    c.n0 = (bid & 1) * CTAN;
    c.wm = (wid & 1) * 64;
    c.wn = (wid >> 1) * 64;
    c.sbase = smem_u32(dyn);
    const int l = c.lane;
    c.aoff = (uint32_t)((l & 15) * ROWB + ((l >> 4) & 1) * 16);
    c.boff = (uint32_t)(((l & 7) + ((l >> 4) & 1) * 8) * ROWB + ((l >> 3) & 1) * 16);
}

__device__ __forceinline__ void load_tile(const GemmCore& c,
                                          const __half* __restrict__ Ag, int strideA,
                                          const __half* __restrict__ Bg, int strideB,
                                          int t) {
    const int tid = threadIdx.x;
    const int k0 = t * CTAK;
    const uint32_t stA = c.sbase + (uint32_t)(t & (NSTAGE - 1)) * STAGEB;
    const uint32_t stB = stA + ABYTES;
#pragma unroll
    for (int i = 0; i < 2; i++) {
        int ch = tid + i * 256;
        int r = ch >> 2, q = ch & 3;
        CP_ASYNC16(stA + (uint32_t)(r * ROWB + q * 16),
                   Ag + (size_t)(c.m0 + r) * strideA + k0 + q * 8);
    }
#pragma unroll
    for (int i = 0; i < 4; i++) {
        int ch = tid + i * 256;
        int r = ch >> 2, q = ch & 3;
        CP_ASYNC16(stB + (uint32_t)(r * ROWB + q * 16),
                   Bg + (size_t)(c.n0 + r) * strideB + k0 + q * 8);
    }
}

// Load all fragments for k-half s (s in {0,1}) of tile t.
__device__ __forceinline__ void lds_frags(const GemmCore& c, int t, int s,
                                          uint32_t a[4][4], uint32_t b[8][2]) {
    const uint32_t stA = c.sbase + (uint32_t)(t & (NSTAGE - 1)) * STAGEB;
    const uint32_t stB = stA + ABYTES;
#pragma unroll
    for (int i = 0; i < 4; i++)
        LDSM4(a[i][0], a[i][1], a[i][2], a[i][3],
              stA + (uint32_t)((c.wm + 16 * i) * ROWB + s * 32) + c.aoff);
#pragma unroll
    for (int jp = 0; jp < 4; jp++)
        LDSM4(b[2 * jp][0], b[2 * jp][1], b[2 * jp + 1][0], b[2 * jp + 1][1],
              stB + (uint32_t)((c.wn + 16 * jp) * ROWB + s * 32) + c.boff);
}

__device__ __forceinline__ void mma_all(float acc[4][8][4],
                                        uint32_t a[4][4], uint32_t b[8][2]) {
#pragma unroll
    for (int i = 0; i < 4; i++)
#pragma unroll
        for (int j = 0; j < 8; j++)
            MMA_F16(acc[i][j], a[i], b[j][0], b[j][1]);
}

// Pipelined mainloop shared by both gemms (EXACT R4 schedule).
__device__ __forceinline__ void gemm_mainloop(const GemmCore& c,
                                              const __half* __restrict__ Ag, int strideA,
                                              const __half* __restrict__ Bg, int strideB,
                                              int ntiles, float acc[4][8][4]) {
    // prologue: stages 0..2
#pragma unroll
    for (int s = 0; s < NSTAGE - 1; s++) {
        load_tile(c, Ag, strideA, Bg, strideB, s);
        CP_COMMIT();
    }
    CP_WAITG2();                 // tile 0 resident
    __syncthreads();

    uint32_t a0[4][4], b0[8][2], a1[4][4], b1[8][2];
    lds_frags(c, 0, 0, a0, b0);

    for (int t = 0; t < ntiles; t++) {
        if (t + NSTAGE - 1 < ntiles)
            load_tile(c, Ag, strideA, Bg, strideB, t + NSTAGE - 1);
        CP_COMMIT();                     // uniform group count per iter
        lds_frags(c, t, 1, a1, b1);      // overlaps with mma below
        mma_all(acc, a0, b0);
        if (t + 1 < ntiles) {
            CP_WAITG2();                 // tile t+1 resident
            __syncthreads();             // stage slot (t+3)&3 safe to refill next iter
            lds_frags(c, t + 1, 0, a0, b0);  // overlaps with mma below
        }
        mma_all(acc, a1, b1);
    }
}

// ---------------------------------------------------------------------------
// Kernel 4: support = d_i * ( adj_h @ xsT^T + d_i * x_i )   -> fp16
// ---------------------------------------------------------------------------
__global__ __launch_bounds__(256, 1) void gemm1_h(const float* __restrict__ x) {
    extern __shared__ __align__(128) char dyn[];
    GemmCore c;
    core_init(c, dyn, blockIdx.x);

    float acc[4][8][4];
#pragma unroll
    for (int i = 0; i < 4; i++)
#pragma unroll
        for (int j = 0; j < 8; j++)
#pragma unroll
            for (int q = 0; q < 4; q++) acc[i][j][q] = 0.f;

    gemm_mainloop(c, g_adj_h, NROWS, g_xsT, NROWS, NT1, acc);

    // epilogue: support = half( d_m * (acc + d_m * x) )
    const int g = c.lane >> 2, tg = c.lane & 3;
#pragma unroll
    for (int i = 0; i < 4; i++) {
        const int r0 = c.m0 + c.wm + 16 * i + g;
        const int r1 = r0 + 8;
        const float d0 = g_deg[r0], d1 = g_deg[r1];
#pragma unroll
        for (int j = 0; j < 8; j++) {
            const int col = c.n0 + c.wn + 8 * j + 2 * tg;
            float2 x0 = *reinterpret_cast<const float2*>(&x[(size_t)r0 * DIN + col]);
            float2 x1 = *reinterpret_cast<const float2*>(&x[(size_t)r1 * DIN + col]);
            __half2 h0 = __floats2half2_rn(d0 * (acc[i][j][0] + d0 * x0.x),
                                           d0 * (acc[i][j][1] + d0 * x0.y));
            __half2 h1 = __floats2half2_rn(d1 * (acc[i][j][2] + d1 * x1.x),
                                           d1 * (acc[i][j][3] + d1 * x1.y));
            *reinterpret_cast<__half2*>(&g_support[(size_t)r0 * DIN + col]) = h0;
            *reinterpret_cast<__half2*>(&g_support[(size_t)r1 * DIN + col]) = h1;
        }
    }
}

// ---------------------------------------------------------------------------
// Kernel 5: out = relu(support @ Wh^T + b)   -> fp32
// ---------------------------------------------------------------------------
__global__ __launch_bounds__(256, 1) void gemm2_h(const float* __restrict__ bias,
                                                  float* __restrict__ out) {
    extern __shared__ __align__(128) char dyn[];
    GemmCore c;
    core_init(c, dyn, blockIdx.x);

    float acc[4][8][4];
#pragma unroll
    for (int i = 0; i < 4; i++)
#pragma unroll
        for (int j = 0; j < 8; j++)
#pragma unroll
            for (int q = 0; q < 4; q++) acc[i][j][q] = 0.f;

    gemm_mainloop(c, g_support, DIN, g_Wh, DIN, NT2, acc);

    const int g = c.lane >> 2, tg = c.lane & 3;
#pragma unroll
    for (int i = 0; i < 4; i++) {
        const int r0 = c.m0 + c.wm + 16 * i + g;
        const int r1 = r0 + 8;
#pragma unroll
        for (int j = 0; j < 8; j++) {
            const int col = c.n0 + c.wn + 8 * j + 2 * tg;
            float2 bv = *reinterpret_cast<const float2*>(&bias[col]);
            float2 o0, o1;
            o0.x = fmaxf(acc[i][j][0] + bv.x, 0.f);
            o0.y = fmaxf(acc[i][j][1] + bv.y, 0.f);
            o1.x = fmaxf(acc[i][j][2] + bv.x, 0.f);
            o1.y = fmaxf(acc[i][j][3] + bv.y, 0.f);
            *reinterpret_cast<float2*>(&out[(size_t)r0 * DOUT + col]) = o0;
            *reinterpret_cast<float2*>(&out[(size_t)r1 * DOUT + col]) = o1;
        }
    }
}

// ---------------------------------------------------------------------------
extern "C" void kernel_launch(void* const* d_in, const int* in_sizes, int n_in,
                              void* d_out, int out_size) {
    const float* x = nullptr;
    const float* adj = nullptr;
    const float* W = nullptr;
    const float* b = nullptr;
    for (int i = 0; i < n_in; i++) {
        long sz = (long)in_sizes[i];
        if (sz == (long)NROWS * NROWS)      adj = (const float*)d_in[i];
        else if (sz == (long)NROWS * DIN)   x   = (const float*)d_in[i];
        else if (sz == (long)DIN * DOUT)    W   = (const float*)d_in[i];
        else if (sz == (long)DOUT)          b   = (const float*)d_in[i];
    }
    float* out = (float*)d_out;

    cudaFuncSetAttribute(gemm1_h, cudaFuncAttributeMaxDynamicSharedMemorySize, DYN_SMEM);
    cudaFuncSetAttribute(gemm2_h, cudaFuncAttributeMaxDynamicSharedMemorySize, DYN_SMEM);

    rowsum_convert<<<NROWS / 2, 256>>>(adj);
    scale_transpose_h<<<dim3(NROWS / 32, DIN / 32), 256>>>(x);
    w_convert<<<(DOUT * DIN / 4) / 256, 256>>>(W);
    gemm1_h<<<(NROWS / CTAM) * (DIN / CTAN), 256, DYN_SMEM>>>(x);
    gemm2_h<<<(NROWS / CTAM) * (DOUT / CTAN), 256, DYN_SMEM>>>(b, out);
}